// round 2
// baseline (speedup 1.0000x reference)
#include <cuda_runtime.h>
#include <math.h>

#define NBATCH 64
#define NSTEP  1024
#define NIN    256
#define NH     512

#define WROW 516  // padded k-stride (floats) for weight smem rows: (4*jl + k) % 32 distinct per phase
#define SMEM_FLOATS (3*32*WROW + 8*768)
#define SMEM_BYTES  (SMEM_FLOATS*4)

// scratch: input projections x[gate][b][t][j], double-buffered h, per-group flags
__device__ float    g_x[(size_t)3*NBATCH*NSTEP*NH];   // ~403 MB
__device__ float    g_h[2*NBATCH*NH];
__device__ unsigned g_flags[128];

__device__ __forceinline__ unsigned ld_acq(const unsigned* p) {
  unsigned v;
  asm volatile("ld.global.acquire.gpu.b32 %0, [%1];" : "=r"(v) : "l"(p) : "memory");
  return v;
}
__device__ __forceinline__ void st_rel(unsigned* p, unsigned v) {
  asm volatile("st.global.release.gpu.b32 [%0], %1;" :: "l"(p), "r"(v) : "memory");
}

__global__ void reset_kernel() { g_flags[threadIdx.x] = 0u; }

// ---------------- input projection GEMM: C[g][m][n] = A[m][:] . W_g[n][:] + b_g[n] ----------------
__global__ void __launch_bounds__(256) xproj_kernel(
    const float* __restrict__ A,
    const float* __restrict__ w0, const float* __restrict__ w1, const float* __restrict__ w2,
    const float* __restrict__ b0, const float* __restrict__ b1, const float* __restrict__ b2)
{
  __shared__ float As[32][68];
  __shared__ float Bs[32][68];
  int g = blockIdx.z;
  const float* W    = (g==0) ? w0 : ((g==1) ? w1 : w2);
  const float* bias = (g==0) ? b0 : ((g==1) ? b1 : b2);
  float* C = g_x + (size_t)g * (size_t)(NBATCH*NSTEP) * NH;

  int m0 = blockIdx.y * 64;
  int n0 = blockIdx.x * 64;
  int tid = threadIdx.x;
  int tx = tid & 15, ty = tid >> 4;
  int lr = tid >> 3;          // 0..31
  int lc = (tid & 7) * 4;     // 0..28

  float acc[4][4] = {};

  for (int k0 = 0; k0 < NIN; k0 += 32) {
    float4 a0 = *(const float4*)(A + (size_t)(m0+lr   )*NIN + k0 + lc);
    float4 a1 = *(const float4*)(A + (size_t)(m0+lr+32)*NIN + k0 + lc);
    float4 v0 = *(const float4*)(W + (size_t)(n0+lr   )*NIN + k0 + lc);
    float4 v1 = *(const float4*)(W + (size_t)(n0+lr+32)*NIN + k0 + lc);
    __syncthreads();
    As[lc+0][lr] = a0.x; As[lc+1][lr] = a0.y; As[lc+2][lr] = a0.z; As[lc+3][lr] = a0.w;
    As[lc+0][lr+32] = a1.x; As[lc+1][lr+32] = a1.y; As[lc+2][lr+32] = a1.z; As[lc+3][lr+32] = a1.w;
    Bs[lc+0][lr] = v0.x; Bs[lc+1][lr] = v0.y; Bs[lc+2][lr] = v0.z; Bs[lc+3][lr] = v0.w;
    Bs[lc+0][lr+32] = v1.x; Bs[lc+1][lr+32] = v1.y; Bs[lc+2][lr+32] = v1.z; Bs[lc+3][lr+32] = v1.w;
    __syncthreads();
    #pragma unroll
    for (int kk = 0; kk < 32; kk++) {
      float4 av = *(const float4*)(&As[kk][ty*4]);
      float4 bv = *(const float4*)(&Bs[kk][tx*4]);
      float a[4] = {av.x, av.y, av.z, av.w};
      float b[4] = {bv.x, bv.y, bv.z, bv.w};
      #pragma unroll
      for (int i = 0; i < 4; i++)
        #pragma unroll
        for (int jj = 0; jj < 4; jj++)
          acc[i][jj] += a[i]*b[jj];
    }
  }

  float4 bv = *(const float4*)(bias + n0 + tx*4);
  #pragma unroll
  for (int i = 0; i < 4; i++) {
    int row = m0 + ty*4 + i;
    float4 o;
    o.x = acc[i][0] + bv.x; o.y = acc[i][1] + bv.y;
    o.z = acc[i][2] + bv.z; o.w = acc[i][3] + bv.w;
    *(float4*)(C + (size_t)row*NH + n0 + tx*4) = o;
  }
}

// ---------------- persistent GRU recurrence ----------------
// 128 CTAs co-resident: blockIdx = bgrp(8) * 16 + jt(16).
// Each CTA owns batches [bgrp*8, bgrp*8+8) x output columns [jt*32, jt*32+32), all 3 gates.
// Recurrent weights live in SMEM for the whole kernel. Per step:
//   stage h (L2, .cg) -> smem; 8-way K-split matvec; smem reduce; pointwise; write h_next;
//   release flag; wait on own batch-group's 16 flags (acquire).
__global__ void __launch_bounds__(256, 1) gru_rec(
    const float* __restrict__ h0,
    const float* __restrict__ w_hr, const float* __restrict__ w_hz, const float* __restrict__ w_hn,
    const float* __restrict__ b_hr, const float* __restrict__ b_hz, const float* __restrict__ b_hn,
    float* __restrict__ out, int write_hlast)
{
  extern __shared__ float sm[];
  float* wsm  = sm;                    // [3][32][WROW]
  float* un   = sm + 3*32*WROW;        // union: hsm [8][512] (16KB) / part [8][768] (24KB)
  float* hsm  = un;
  float* part = un;

  int tid  = threadIdx.x;
  int r    = tid >> 5;                 // k-split 0..7 (== epilogue batch index)
  int jl   = tid & 31;
  int bgrp = blockIdx.x >> 4;
  int jt   = blockIdx.x & 15;
  int j    = jt*32 + jl;

  // load recurrent weights for this j-slice into smem: wsm[g][jl][k], padded rows
  {
    const float* srcs[3] = {w_hr, w_hz, w_hn};
    #pragma unroll
    for (int g = 0; g < 3; g++) {
      const float* wsrc = srcs[g] + (size_t)j*NH;
      float* wdst = wsm + (g*32 + jl)*WROW;
      #pragma unroll
      for (int kk = 0; kk < 64; kk += 4) {
        int k = r*64 + kk;
        *(float4*)(wdst + k) = *(const float4*)(wsrc + k);
      }
    }
  }
  float bhr = b_hr[j], bhz = b_hz[j], bhn = b_hn[j];
  int bb = bgrp*8 + r;                 // epilogue batch

  const float* xr_p = g_x + (size_t)bb*NSTEP*NH + j;
  const float* xz_p = xr_p + (size_t)NBATCH*NSTEP*NH;
  const float* xn_p = xz_p + (size_t)NBATCH*NSTEP*NH;
  float* out_p   = out + (size_t)bb*NSTEP*NH + j;
  float* hlast_p = out + (size_t)NBATCH*NSTEP*NH + (size_t)bb*NH + j;

  unsigned* myflag = g_flags + bgrp*16 + jt;
  const unsigned* gf = g_flags + bgrp*16;

  const float* wr = wsm + (0*32 + jl)*WROW;
  const float* wz = wsm + (1*32 + jl)*WROW;
  const float* wn = wsm + (2*32 + jl)*WROW;
  int k0 = r*64;

  __syncthreads();   // weights visible

  #pragma unroll 1
  for (int t = 0; t < NSTEP; t++) {
    // wait until all 16 producers of this batch group finished step t-1
    if (t > 0 && tid < 16) {
      while (ld_acq(gf + tid) < (unsigned)t) __nanosleep(32);
    }
    __syncthreads();

    // stage h[bgrp*8..+8][0..512) into smem (bypass L1: written by other SMs)
    {
      const float4* src = (t == 0)
        ? (const float4*)(h0 + (size_t)bgrp*8*NH)
        : (const float4*)(g_h + (size_t)((t-1)&1)*NBATCH*NH + (size_t)bgrp*8*NH);
      float4* dst = (float4*)hsm;
      #pragma unroll
      for (int i = 0; i < 4; i++)
        dst[tid + i*256] = __ldcg(src + tid + i*256);
    }
    __syncthreads();

    // K-split matvec: this thread covers k in [r*64, r*64+64) for its j, all 3 gates, 8 batches
    float ar[8] = {}, az[8] = {}, an[8] = {};
    #pragma unroll 4
    for (int kk = 0; kk < 64; kk += 4) {
      int k = k0 + kk;
      float4 vr = *(const float4*)(wr + k);
      float4 vz = *(const float4*)(wz + k);
      float4 vn = *(const float4*)(wn + k);
      #pragma unroll
      for (int b = 0; b < 8; b++) {
        float4 hv = *(const float4*)(hsm + b*NH + k);
        ar[b] += vr.x*hv.x + vr.y*hv.y + vr.z*hv.z + vr.w*hv.w;
        az[b] += vz.x*hv.x + vz.y*hv.y + vz.z*hv.z + vz.w*hv.w;
        an[b] += vn.x*hv.x + vn.y*hv.y + vn.z*hv.z + vn.w*hv.w;
      }
    }
    float h_old = hsm[r*NH + j];       // grab before union region is overwritten
    __syncthreads();

    #pragma unroll
    for (int b = 0; b < 8; b++) {
      part[r*768 +   0 + b*32 + jl] = ar[b];
      part[r*768 + 256 + b*32 + jl] = az[b];
      part[r*768 + 512 + b*32 + jl] = an[b];
    }
    __syncthreads();

    // reduce 8 partials; epilogue thread tid owns (b = tid/32 == r, column j)
    float Sr = 0.f, Sz = 0.f, Sn = 0.f;
    #pragma unroll
    for (int rr = 0; rr < 8; rr++) {
      Sr += part[rr*768 +       tid];
      Sz += part[rr*768 + 256 + tid];
      Sn += part[rr*768 + 512 + tid];
    }
    float xr = xr_p[(size_t)t*NH];
    float xz = xz_p[(size_t)t*NH];
    float xn = xn_p[(size_t)t*NH];
    float rg = 1.f/(1.f + __expf(-(xr + Sr + bhr)));
    float zg = 1.f/(1.f + __expf(-(xz + Sz + bhz)));
    float ng = tanhf(xn + rg*(Sn + bhn));
    float hnew = (1.f - zg)*ng + zg*h_old;

    out_p[(size_t)t*NH] = hnew;
    g_h[(size_t)(t&1)*NBATCH*NH + (size_t)bb*NH + j] = hnew;
    if (write_hlast && t == NSTEP-1) hlast_p[0] = hnew;

    __threadfence();                   // make every thread's h store globally visible
    __syncthreads();
    if (tid == 0) st_rel(myflag, (unsigned)(t+1));
  }
}

extern "C" void kernel_launch(void* const* d_in, const int* in_sizes, int n_in,
                              void* d_out, int out_size) {
  const float* inp  = (const float*)d_in[0];
  const float* h0   = (const float*)d_in[1];
  const float* w_ir = (const float*)d_in[2];
  const float* w_iz = (const float*)d_in[3];
  const float* w_in = (const float*)d_in[4];
  const float* b_ir = (const float*)d_in[5];
  const float* b_iz = (const float*)d_in[6];
  const float* b_in = (const float*)d_in[7];
  const float* w_hr = (const float*)d_in[8];
  const float* w_hz = (const float*)d_in[9];
  const float* w_hn = (const float*)d_in[10];
  const float* b_hr = (const float*)d_in[11];
  const float* b_hz = (const float*)d_in[12];
  const float* b_hn = (const float*)d_in[13];
  float* out = (float*)d_out;

  cudaFuncSetAttribute(gru_rec, cudaFuncAttributeMaxDynamicSharedMemorySize, SMEM_BYTES);

  reset_kernel<<<1, 128>>>();

  dim3 gg(NH/64, (NBATCH*NSTEP)/64, 3);
  xproj_kernel<<<gg, 256>>>(inp, w_ir, w_iz, w_in, b_ir, b_iz, b_in);

  int write_hlast = (out_size >= NBATCH*NSTEP*NH + NBATCH*NH) ? 1 : 0;
  gru_rec<<<128, 256, SMEM_BYTES>>>(h0, w_hr, w_hz, w_hn, b_hr, b_hz, b_hn,
                                    out, write_hlast);
}

// round 3
// speedup vs baseline: 1.2843x; 1.2843x over previous
#include <cuda_runtime.h>
#include <math.h>

#define NBATCH 64
#define NSTEP  1024
#define NIN    256
#define NH     512

#define WROW 516  // padded k-stride (floats): (4*jl + k) % 32 distinct per LDS.128 phase
#define SMEM_FLOATS (3*32*WROW + 8*768)
#define SMEM_BYTES  (SMEM_FLOATS*4)

typedef unsigned long long u64;

// packed fp32x2 FMA: d = a*b + c (elementwise on 2 packed floats) — SASS FFMA2
#define FMA2(acc, a, b) asm("fma.rn.f32x2 %0, %1, %2, %0;" : "+l"(acc) : "l"(a), "l"(b))
#define DUP2(r, x)      asm("mov.b64 %0, {%1, %1};" : "=l"(r) : "f"(x))
#define UNPACK2(lo, hi, v) asm("mov.b64 {%0, %1}, %2;" : "=f"(lo), "=f"(hi) : "l"(v))

// scratch: input projections x[gate][b][t][j], double-buffered h, per-group flags
__device__ float    g_x[(size_t)3*NBATCH*NSTEP*NH];   // ~403 MB
__device__ float    g_h[2*NBATCH*NH];
__device__ unsigned g_flags[128];

__device__ __forceinline__ unsigned ld_acq(const unsigned* p) {
  unsigned v;
  asm volatile("ld.global.acquire.gpu.b32 %0, [%1];" : "=r"(v) : "l"(p) : "memory");
  return v;
}
__device__ __forceinline__ void st_rel(unsigned* p, unsigned v) {
  asm volatile("st.global.release.gpu.b32 [%0], %1;" :: "l"(p), "r"(v) : "memory");
}

// ---------------- input projection GEMM: C[g][m][n] = A[m][:] . W_g[n][:] + b_g[n] ----------------
__global__ void __launch_bounds__(256) xproj_kernel(
    const float* __restrict__ A,
    const float* __restrict__ w0, const float* __restrict__ w1, const float* __restrict__ w2,
    const float* __restrict__ b0, const float* __restrict__ b1, const float* __restrict__ b2)
{
  __shared__ float As[32][68];
  __shared__ float Bs[32][68];

  int tid = threadIdx.x;
  // reset recurrence flags (gru_rec launches after this kernel completes)
  if (blockIdx.x == 0 && blockIdx.y == 0 && blockIdx.z == 0 && tid < 128)
    g_flags[tid] = 0u;

  int g = blockIdx.z;
  const float* W    = (g==0) ? w0 : ((g==1) ? w1 : w2);
  const float* bias = (g==0) ? b0 : ((g==1) ? b1 : b2);
  float* C = g_x + (size_t)g * (size_t)(NBATCH*NSTEP) * NH;

  int m0 = blockIdx.y * 64;
  int n0 = blockIdx.x * 64;
  int tx = tid & 15, ty = tid >> 4;
  int lr = tid >> 3;          // 0..31
  int lc = (tid & 7) * 4;     // 0..28

  u64 acc2[4][2] = {};

  for (int k0 = 0; k0 < NIN; k0 += 32) {
    float4 a0 = *(const float4*)(A + (size_t)(m0+lr   )*NIN + k0 + lc);
    float4 a1 = *(const float4*)(A + (size_t)(m0+lr+32)*NIN + k0 + lc);
    float4 v0 = *(const float4*)(W + (size_t)(n0+lr   )*NIN + k0 + lc);
    float4 v1 = *(const float4*)(W + (size_t)(n0+lr+32)*NIN + k0 + lc);
    __syncthreads();
    As[lc+0][lr] = a0.x; As[lc+1][lr] = a0.y; As[lc+2][lr] = a0.z; As[lc+3][lr] = a0.w;
    As[lc+0][lr+32] = a1.x; As[lc+1][lr+32] = a1.y; As[lc+2][lr+32] = a1.z; As[lc+3][lr+32] = a1.w;
    Bs[lc+0][lr] = v0.x; Bs[lc+1][lr] = v0.y; Bs[lc+2][lr] = v0.z; Bs[lc+3][lr] = v0.w;
    Bs[lc+0][lr+32] = v1.x; Bs[lc+1][lr+32] = v1.y; Bs[lc+2][lr+32] = v1.z; Bs[lc+3][lr+32] = v1.w;
    __syncthreads();
    #pragma unroll
    for (int kk = 0; kk < 32; kk++) {
      float4 av = *(const float4*)(&As[kk][ty*4]);
      ulonglong2 bp = *(const ulonglong2*)(&Bs[kk][tx*4]);
      u64 d0, d1, d2, d3;
      DUP2(d0, av.x); DUP2(d1, av.y); DUP2(d2, av.z); DUP2(d3, av.w);
      FMA2(acc2[0][0], d0, bp.x); FMA2(acc2[0][1], d0, bp.y);
      FMA2(acc2[1][0], d1, bp.x); FMA2(acc2[1][1], d1, bp.y);
      FMA2(acc2[2][0], d2, bp.x); FMA2(acc2[2][1], d2, bp.y);
      FMA2(acc2[3][0], d3, bp.x); FMA2(acc2[3][1], d3, bp.y);
    }
  }

  float4 bv = *(const float4*)(bias + n0 + tx*4);
  #pragma unroll
  for (int i = 0; i < 4; i++) {
    int row = m0 + ty*4 + i;
    float c0, c1, c2, c3;
    UNPACK2(c0, c1, acc2[i][0]);
    UNPACK2(c2, c3, acc2[i][1]);
    float4 o;
    o.x = c0 + bv.x; o.y = c1 + bv.y;
    o.z = c2 + bv.z; o.w = c3 + bv.w;
    *(float4*)(C + (size_t)row*NH + n0 + tx*4) = o;
  }
}

// ---------------- persistent GRU recurrence ----------------
// 128 CTAs co-resident: blockIdx = bgrp(8) * 16 + jt(16).
// Each CTA owns batches [bgrp*8, bgrp*8+8) x output columns [jt*32, jt*32+32), all 3 gates.
// Recurrent weights live in SMEM for the whole kernel. Per step:
//   prefetch x; wait group flags; stage h (L2, .cg) -> smem; 8-way K-split FFMA2 matvec;
//   smem reduce; pointwise; write h_next; release flag (no MEMBAR.GPU needed).
__global__ void __launch_bounds__(256, 1) gru_rec(
    const float* __restrict__ h0,
    const float* __restrict__ w_hr, const float* __restrict__ w_hz, const float* __restrict__ w_hn,
    const float* __restrict__ b_hr, const float* __restrict__ b_hz, const float* __restrict__ b_hn,
    float* __restrict__ out, int write_hlast)
{
  extern __shared__ float sm[];
  float* wsm  = sm;                    // [3][32][WROW]
  float* un   = sm + 3*32*WROW;        // union: hsm [8][512] (16KB) / part [8][768] (24KB)
  float* hsm  = un;
  float* part = un;

  int tid  = threadIdx.x;
  int r    = tid >> 5;                 // k-split 0..7 (== epilogue batch index)
  int jl   = tid & 31;
  int bgrp = blockIdx.x >> 4;
  int jt   = blockIdx.x & 15;
  int j    = jt*32 + jl;

  // load recurrent weights for this j-slice into smem: wsm[g][jl][k], padded rows
  {
    const float* srcs[3] = {w_hr, w_hz, w_hn};
    #pragma unroll
    for (int g = 0; g < 3; g++) {
      const float* wsrc = srcs[g] + (size_t)j*NH;
      float* wdst = wsm + (g*32 + jl)*WROW;
      #pragma unroll
      for (int kk = 0; kk < 64; kk += 4) {
        int k = r*64 + kk;
        *(float4*)(wdst + k) = *(const float4*)(wsrc + k);
      }
    }
  }
  float bhr = b_hr[j], bhz = b_hz[j], bhn = b_hn[j];
  int bb = bgrp*8 + r;                 // epilogue batch

  const float* xr_p = g_x + (size_t)bb*NSTEP*NH + j;
  const float* xz_p = xr_p + (size_t)NBATCH*NSTEP*NH;
  const float* xn_p = xz_p + (size_t)NBATCH*NSTEP*NH;
  float* out_p   = out + (size_t)bb*NSTEP*NH + j;
  float* hlast_p = out + (size_t)NBATCH*NSTEP*NH + (size_t)bb*NH + j;

  unsigned* myflag = g_flags + bgrp*16 + jt;
  const unsigned* gf = g_flags + bgrp*16;

  const float* wr = wsm + (0*32 + jl)*WROW;
  const float* wz = wsm + (1*32 + jl)*WROW;
  const float* wn = wsm + (2*32 + jl)*WROW;
  int k0 = r*64;

  __syncthreads();   // weights visible

  #pragma unroll 1
  for (int t = 0; t < NSTEP; t++) {
    // prefetch this step's input-projection contributions (independent of peers)
    float xr = __ldcs(xr_p + (size_t)t*NH);
    float xz = __ldcs(xz_p + (size_t)t*NH);
    float xn = __ldcs(xn_p + (size_t)t*NH);

    // wait until all 16 producers of this batch group finished step t-1
    if (t > 0 && tid < 16) {
      while (ld_acq(gf + tid) < (unsigned)t) { }
    }
    __syncthreads();

    // stage h[bgrp*8..+8][0..512) into smem (bypass L1: written by other SMs)
    {
      const float4* src = (t == 0)
        ? (const float4*)(h0 + (size_t)bgrp*8*NH)
        : (const float4*)(g_h + (size_t)((t-1)&1)*NBATCH*NH + (size_t)bgrp*8*NH);
      float4* dst = (float4*)hsm;
      #pragma unroll
      for (int i = 0; i < 4; i++)
        dst[tid + i*256] = __ldcg(src + tid + i*256);
    }
    __syncthreads();

    // K-split matvec: this thread covers k in [r*64, r*64+64) for its j, all 3 gates, 8 batches
    // packed fp32x2 accumulation along k (horizontal add at the end)
    u64 ar2[8] = {}, az2[8] = {}, an2[8] = {};
    #pragma unroll 4
    for (int kk = 0; kk < 64; kk += 4) {
      int k = k0 + kk;
      ulonglong2 vr = *(const ulonglong2*)(wr + k);
      ulonglong2 vz = *(const ulonglong2*)(wz + k);
      ulonglong2 vn = *(const ulonglong2*)(wn + k);
      #pragma unroll
      for (int b = 0; b < 8; b++) {
        ulonglong2 hv = *(const ulonglong2*)(hsm + b*NH + k);
        FMA2(ar2[b], vr.x, hv.x); FMA2(ar2[b], vr.y, hv.y);
        FMA2(az2[b], vz.x, hv.x); FMA2(az2[b], vz.y, hv.y);
        FMA2(an2[b], vn.x, hv.x); FMA2(an2[b], vn.y, hv.y);
      }
    }
    float h_old = hsm[r*NH + j];       // grab before union region is overwritten
    __syncthreads();

    #pragma unroll
    for (int b = 0; b < 8; b++) {
      float lo, hi;
      UNPACK2(lo, hi, ar2[b]); part[r*768 +   0 + b*32 + jl] = lo + hi;
      UNPACK2(lo, hi, az2[b]); part[r*768 + 256 + b*32 + jl] = lo + hi;
      UNPACK2(lo, hi, an2[b]); part[r*768 + 512 + b*32 + jl] = lo + hi;
    }
    __syncthreads();

    // reduce 8 partials; epilogue thread tid owns (b = tid/32 == r, column j)
    float Sr = 0.f, Sz = 0.f, Sn = 0.f;
    #pragma unroll
    for (int rr = 0; rr < 8; rr++) {
      Sr += part[rr*768 +       tid];
      Sz += part[rr*768 + 256 + tid];
      Sn += part[rr*768 + 512 + tid];
    }
    float rg = 1.f/(1.f + __expf(-(xr + Sr + bhr)));
    float zg = 1.f/(1.f + __expf(-(xz + Sz + bhz)));
    float ng = tanhf(xn + rg*(Sn + bhn));
    float hnew = (1.f - zg)*ng + zg*h_old;

    __stcs(out_p + (size_t)t*NH, hnew);
    g_h[(size_t)(t&1)*NBATCH*NH + (size_t)bb*NH + j] = hnew;
    if (write_hlast && t == NSTEP-1) hlast_p[0] = hnew;

    // bar.sync + release-store establishes happens-before for ALL threads' h stores
    __syncthreads();
    if (tid == 0) st_rel(myflag, (unsigned)(t+1));
  }
}

extern "C" void kernel_launch(void* const* d_in, const int* in_sizes, int n_in,
                              void* d_out, int out_size) {
  const float* inp  = (const float*)d_in[0];
  const float* h0   = (const float*)d_in[1];
  const float* w_ir = (const float*)d_in[2];
  const float* w_iz = (const float*)d_in[3];
  const float* w_in = (const float*)d_in[4];
  const float* b_ir = (const float*)d_in[5];
  const float* b_iz = (const float*)d_in[6];
  const float* b_in = (const float*)d_in[7];
  const float* w_hr = (const float*)d_in[8];
  const float* w_hz = (const float*)d_in[9];
  const float* w_hn = (const float*)d_in[10];
  const float* b_hr = (const float*)d_in[11];
  const float* b_hz = (const float*)d_in[12];
  const float* b_hn = (const float*)d_in[13];
  float* out = (float*)d_out;

  cudaFuncSetAttribute(gru_rec, cudaFuncAttributeMaxDynamicSharedMemorySize, SMEM_BYTES);

  dim3 gg(NH/64, (NBATCH*NSTEP)/64, 3);
  xproj_kernel<<<gg, 256>>>(inp, w_ir, w_iz, w_in, b_ir, b_iz, b_in);

  int write_hlast = (out_size >= NBATCH*NSTEP*NH + NBATCH*NH) ? 1 : 0;
  gru_rec<<<128, 256, SMEM_BYTES>>>(h0, w_hr, w_hz, w_hn, b_hr, b_hz, b_hn,
                                    out, write_hlast);
}

// round 4
// speedup vs baseline: 1.2996x; 1.0119x over previous
#include <cuda_runtime.h>
#include <math.h>

#define NBATCH 64
#define NSTEP  1024
#define NIN    256
#define NH     512

#define WROW 516  // padded k-stride (floats): (4*jl + k) % 32 distinct per LDS.128 phase
#define SMEM_FLOATS (3*32*WROW + 8*768)
#define SMEM_BYTES  (SMEM_FLOATS*4)

typedef unsigned long long u64;

// packed fp32x2 FMA: d = a*b + c (elementwise on 2 packed floats) — SASS FFMA2
#define FMA2(acc, a, b) asm("fma.rn.f32x2 %0, %1, %2, %0;" : "+l"(acc) : "l"(a), "l"(b))
#define DUP2(r, x)      asm("mov.b64 %0, {%1, %1};" : "=l"(r) : "f"(x))
#define UNPACK2(lo, hi, v) asm("mov.b64 {%0, %1}, %2;" : "=f"(lo), "=f"(hi) : "l"(v))

// scratch: input projections x[gate][b][t][j], double-buffered h, per-group flags
__device__ float    g_x[(size_t)3*NBATCH*NSTEP*NH];   // ~403 MB
__device__ float    g_h[2*NBATCH*NH];
__device__ unsigned g_flags[128];

__device__ __forceinline__ unsigned ld_acq(const unsigned* p) {
  unsigned v;
  asm volatile("ld.global.acquire.gpu.b32 %0, [%1];" : "=r"(v) : "l"(p) : "memory");
  return v;
}
__device__ __forceinline__ void st_rel(unsigned* p, unsigned v) {
  asm volatile("st.global.release.gpu.b32 [%0], %1;" :: "l"(p), "r"(v) : "memory");
}

// ---------------- input projection GEMM: C[g][m][n] = A[m][:] . W_g[n][:] + b_g[n] ----------------
__global__ void __launch_bounds__(256) xproj_kernel(
    const float* __restrict__ A,
    const float* __restrict__ w0, const float* __restrict__ w1, const float* __restrict__ w2,
    const float* __restrict__ b0, const float* __restrict__ b1, const float* __restrict__ b2)
{
  __shared__ float As[32][68];
  __shared__ float Bs[32][68];

  int tid = threadIdx.x;
  if (blockIdx.x == 0 && blockIdx.y == 0 && blockIdx.z == 0 && tid < 128)
    g_flags[tid] = 0u;

  int g = blockIdx.z;
  const float* W    = (g==0) ? w0 : ((g==1) ? w1 : w2);
  const float* bias = (g==0) ? b0 : ((g==1) ? b1 : b2);
  float* C = g_x + (size_t)g * (size_t)(NBATCH*NSTEP) * NH;

  int m0 = blockIdx.y * 64;
  int n0 = blockIdx.x * 64;
  int tx = tid & 15, ty = tid >> 4;
  int lr = tid >> 3;
  int lc = (tid & 7) * 4;

  u64 acc2[4][2] = {};

  for (int k0 = 0; k0 < NIN; k0 += 32) {
    float4 a0 = *(const float4*)(A + (size_t)(m0+lr   )*NIN + k0 + lc);
    float4 a1 = *(const float4*)(A + (size_t)(m0+lr+32)*NIN + k0 + lc);
    float4 v0 = *(const float4*)(W + (size_t)(n0+lr   )*NIN + k0 + lc);
    float4 v1 = *(const float4*)(W + (size_t)(n0+lr+32)*NIN + k0 + lc);
    __syncthreads();
    As[lc+0][lr] = a0.x; As[lc+1][lr] = a0.y; As[lc+2][lr] = a0.z; As[lc+3][lr] = a0.w;
    As[lc+0][lr+32] = a1.x; As[lc+1][lr+32] = a1.y; As[lc+2][lr+32] = a1.z; As[lc+3][lr+32] = a1.w;
    Bs[lc+0][lr] = v0.x; Bs[lc+1][lr] = v0.y; Bs[lc+2][lr] = v0.z; Bs[lc+3][lr] = v0.w;
    Bs[lc+0][lr+32] = v1.x; Bs[lc+1][lr+32] = v1.y; Bs[lc+2][lr+32] = v1.z; Bs[lc+3][lr+32] = v1.w;
    __syncthreads();
    #pragma unroll
    for (int kk = 0; kk < 32; kk++) {
      float4 av = *(const float4*)(&As[kk][ty*4]);
      ulonglong2 bp = *(const ulonglong2*)(&Bs[kk][tx*4]);
      u64 d0, d1, d2, d3;
      DUP2(d0, av.x); DUP2(d1, av.y); DUP2(d2, av.z); DUP2(d3, av.w);
      FMA2(acc2[0][0], d0, bp.x); FMA2(acc2[0][1], d0, bp.y);
      FMA2(acc2[1][0], d1, bp.x); FMA2(acc2[1][1], d1, bp.y);
      FMA2(acc2[2][0], d2, bp.x); FMA2(acc2[2][1], d2, bp.y);
      FMA2(acc2[3][0], d3, bp.x); FMA2(acc2[3][1], d3, bp.y);
    }
  }

  float4 bv = *(const float4*)(bias + n0 + tx*4);
  #pragma unroll
  for (int i = 0; i < 4; i++) {
    int row = m0 + ty*4 + i;
    float c0, c1, c2, c3;
    UNPACK2(c0, c1, acc2[i][0]);
    UNPACK2(c2, c3, acc2[i][1]);
    float4 o;
    o.x = c0 + bv.x; o.y = c1 + bv.y;
    o.z = c2 + bv.z; o.w = c3 + bv.w;
    *(float4*)(C + (size_t)row*NH + n0 + tx*4) = o;
  }
}

// ---------------- persistent GRU recurrence ----------------
// 128 CTAs co-resident: blockIdx = bgrp(8)*16 + jt(16).
// 512 threads: r = tid>>5 in 0..15 (k-split 16, 32 k's each), jl = tid&31 (j column).
// Paired-warp reduce: warps 8..15 dump partials, warps 0..7 add partner row in place,
// then the 8-way epilogue reduce (threads 0..255) as before.
__global__ void __launch_bounds__(512, 1) gru_rec(
    const float* __restrict__ h0,
    const float* __restrict__ w_hr, const float* __restrict__ w_hz, const float* __restrict__ w_hn,
    const float* __restrict__ b_hr, const float* __restrict__ b_hz, const float* __restrict__ b_hn,
    float* __restrict__ out, int write_hlast)
{
  extern __shared__ float sm[];
  float* wsm  = sm;                    // [3][32][WROW]  (~193.5 KB)
  float* un   = sm + 3*32*WROW;        // union: hsm [8][512] (16KB) / part [8][768] (24KB)
  float* hsm  = un;
  float* part = un;

  int tid  = threadIdx.x;
  int r    = tid >> 5;                 // 0..15 k-split
  int jl   = tid & 31;
  int bgrp = blockIdx.x >> 4;
  int jt   = blockIdx.x & 15;
  int j    = jt*32 + jl;
  int k0   = r*32;

  // load recurrent weights for this j-slice into smem: wsm[g][jl][k]
  {
    const float* srcs[3] = {w_hr, w_hz, w_hn};
    #pragma unroll
    for (int g = 0; g < 3; g++) {
      const float* wsrc = srcs[g] + (size_t)j*NH;
      float* wdst = wsm + (g*32 + jl)*WROW;
      #pragma unroll
      for (int kk = 0; kk < 32; kk += 4)
        *(float4*)(wdst + k0 + kk) = *(const float4*)(wsrc + k0 + kk);
    }
  }
  float bhr = b_hr[j], bhz = b_hz[j], bhn = b_hn[j];
  int bb = bgrp*8 + r;                 // epilogue batch (valid for r<8)

  const float* xr_p = g_x + (size_t)bb*NSTEP*NH + j;
  const float* xz_p = xr_p + (size_t)NBATCH*NSTEP*NH;
  const float* xn_p = xz_p + (size_t)NBATCH*NSTEP*NH;
  float* out_p   = out + (size_t)bb*NSTEP*NH + j;
  float* hlast_p = out + (size_t)NBATCH*NSTEP*NH + (size_t)bb*NH + j;

  unsigned* myflag = g_flags + bgrp*16 + jt;
  const unsigned* gf = g_flags + bgrp*16;

  const float* wr = wsm + (0*32 + jl)*WROW;
  const float* wz = wsm + (1*32 + jl)*WROW;
  const float* wn = wsm + (2*32 + jl)*WROW;

  __syncthreads();   // weights visible

  #pragma unroll 1
  for (int t = 0; t < NSTEP; t++) {
    // prefetch this step's input-projection contributions (epilogue threads only)
    float xr = 0.f, xz = 0.f, xn = 0.f;
    if (r < 8) {
      xr = __ldcs(xr_p + (size_t)t*NH);
      xz = __ldcs(xz_p + (size_t)t*NH);
      xn = __ldcs(xn_p + (size_t)t*NH);
    }

    // wait until all 16 producers of this batch group finished step t-1
    if (t > 0 && tid < 16) {
      while (ld_acq(gf + tid) < (unsigned)t) { }
    }
    __syncthreads();                                    // B1

    // stage h[bgrp*8..+8][0..512) into smem (bypass L1)
    {
      const float4* src = (t == 0)
        ? (const float4*)(h0 + (size_t)bgrp*8*NH)
        : (const float4*)(g_h + (size_t)((t-1)&1)*NBATCH*NH + (size_t)bgrp*8*NH);
      float4* dst = (float4*)hsm;
      dst[tid]       = __ldcg(src + tid);
      dst[tid + 512] = __ldcg(src + tid + 512);
    }
    __syncthreads();                                    // B2

    // K-split matvec: k in [r*32, r*32+32), all 3 gates, 8 batches, packed fp32x2
    u64 ar2[8] = {}, az2[8] = {}, an2[8] = {};
    #pragma unroll 2
    for (int kk = 0; kk < 32; kk += 4) {
      int k = k0 + kk;
      ulonglong2 vr = *(const ulonglong2*)(wr + k);
      ulonglong2 vz = *(const ulonglong2*)(wz + k);
      ulonglong2 vn = *(const ulonglong2*)(wn + k);
      #pragma unroll
      for (int b = 0; b < 8; b++) {
        ulonglong2 hv = *(const ulonglong2*)(hsm + b*NH + k);
        FMA2(ar2[b], vr.x, hv.x); FMA2(ar2[b], vr.y, hv.y);
        FMA2(az2[b], vz.x, hv.x); FMA2(az2[b], vz.y, hv.y);
        FMA2(an2[b], vn.x, hv.x); FMA2(an2[b], vn.y, hv.y);
      }
    }
    float h_old = (r < 8) ? hsm[r*NH + j] : 0.f;   // grab before union overwrite

    // horizontal sums
    float sr[8], sz[8], sn[8];
    #pragma unroll
    for (int b = 0; b < 8; b++) {
      float lo, hi;
      UNPACK2(lo, hi, ar2[b]); sr[b] = lo + hi;
      UNPACK2(lo, hi, az2[b]); sz[b] = lo + hi;
      UNPACK2(lo, hi, an2[b]); sn[b] = lo + hi;
    }
    __syncthreads();                                    // B3 (h reads done)

    // warps 8..15 dump partials into row (r-8)
    if (r >= 8) {
      int row = (r - 8)*768;
      #pragma unroll
      for (int b = 0; b < 8; b++) {
        part[row +   0 + b*32 + jl] = sr[b];
        part[row + 256 + b*32 + jl] = sz[b];
        part[row + 512 + b*32 + jl] = sn[b];
      }
    }
    __syncthreads();                                    // B4

    // warps 0..7 add partner row in place
    if (r < 8) {
      int row = r*768;
      #pragma unroll
      for (int b = 0; b < 8; b++) {
        part[row +   0 + b*32 + jl] += sr[b];
        part[row + 256 + b*32 + jl] += sz[b];
        part[row + 512 + b*32 + jl] += sn[b];
      }
    }
    __syncthreads();                                    // B5

    // epilogue: threads 0..255, thread tid owns (b = tid>>5, column j)
    if (tid < 256) {
      float Sr = 0.f, Sz = 0.f, Sn = 0.f;
      #pragma unroll
      for (int rr = 0; rr < 8; rr++) {
        Sr += part[rr*768 +       tid];
        Sz += part[rr*768 + 256 + tid];
        Sn += part[rr*768 + 512 + tid];
      }
      float rg = 1.f/(1.f + __expf(-(xr + Sr + bhr)));
      float zg = 1.f/(1.f + __expf(-(xz + Sz + bhz)));
      float ng = tanhf(xn + rg*(Sn + bhn));
      float hnew = (1.f - zg)*ng + zg*h_old;

      __stcs(out_p + (size_t)t*NH, hnew);
      g_h[(size_t)(t&1)*NBATCH*NH + (size_t)bb*NH + j] = hnew;
      if (write_hlast && t == NSTEP-1) hlast_p[0] = hnew;
    }

    // bar.sync + release-store gives happens-before for all h stores
    __syncthreads();                                    // B6
    if (tid == 0) st_rel(myflag, (unsigned)(t+1));
  }
}

extern "C" void kernel_launch(void* const* d_in, const int* in_sizes, int n_in,
                              void* d_out, int out_size) {
  const float* inp  = (const float*)d_in[0];
  const float* h0   = (const float*)d_in[1];
  const float* w_ir = (const float*)d_in[2];
  const float* w_iz = (const float*)d_in[3];
  const float* w_in = (const float*)d_in[4];
  const float* b_ir = (const float*)d_in[5];
  const float* b_iz = (const float*)d_in[6];
  const float* b_in = (const float*)d_in[7];
  const float* w_hr = (const float*)d_in[8];
  const float* w_hz = (const float*)d_in[9];
  const float* w_hn = (const float*)d_in[10];
  const float* b_hr = (const float*)d_in[11];
  const float* b_hz = (const float*)d_in[12];
  const float* b_hn = (const float*)d_in[13];
  float* out = (float*)d_out;

  cudaFuncSetAttribute(gru_rec, cudaFuncAttributeMaxDynamicSharedMemorySize, SMEM_BYTES);

  dim3 gg(NH/64, (NBATCH*NSTEP)/64, 3);
  xproj_kernel<<<gg, 256>>>(inp, w_ir, w_iz, w_in, b_ir, b_iz, b_in);

  int write_hlast = (out_size >= NBATCH*NSTEP*NH + NBATCH*NH) ? 1 : 0;
  gru_rec<<<128, 512, SMEM_BYTES>>>(h0, w_hr, w_hz, w_hn, b_hr, b_hz, b_hn,
                                    out, write_hlast);
}